// round 7
// baseline (speedup 1.0000x reference)
#include <cuda_runtime.h>
#include <math.h>

#define BATCH 64
#define CH 512
#define WD 512
#define NPIX 16
#define NCOL (CH*NPIX)   /* 8192 */
#define KC 64            /* k-tile */
#define TN 64            /* n-tile = 4 out-ch x 16 px */
#define KHALF 256        /* k per CTA (split-K 2) */

// ---- scratch (allocation-free rule: __device__ globals) ----
__device__ __align__(16) float g_sT[CH*BATCH];        // style transposed [i][b]
__device__ __align__(16) float g_s2[BATCH*CH];        // style^2, b-major [b][i]
__device__ __align__(16) float g_qT[CH*CH];           // q[i][o] (1MB)
__device__ __align__(16) float g_d [BATCH*CH];        // demod factors [b][o]
__device__ __align__(16) float g_part[2][BATCH*NCOL]; // split-K partials (4MB)

union F2 { float2 f; unsigned long long u; };
__device__ __forceinline__ void fma2(F2& d, F2 a, F2 b) {
    asm("fma.rn.f32x2 %0, %1, %2, %0;" : "+l"(d.u) : "l"(a.u), "l"(b.u));
}

// ---------------- Kernel A: style dense  s = w0 @ (mod_w/sqrt(512)) + mod_b + 1
__global__ __launch_bounds__(256) void style_kernel(
        const float* __restrict__ w0,
        const float* __restrict__ mod_w,
        const float* __restrict__ mod_b) {
    __shared__ float w0s[64][68];
    __shared__ float mwsT[8][68];
    const int tid = threadIdx.x;
    const int c  = tid & 7;
    const int bg = tid >> 3;         // 0..31 (2 b each)
    const int c0 = blockIdx.x * 8;

    float acc0 = 0.f, acc1 = 0.f;

    for (int jt = 0; jt < 8; jt++) {
        #pragma unroll
        for (int q = 0; q < 4; q++) {
            int f = tid + q*256;
            int b = f >> 4, jq = f & 15;
            *(float4*)&w0s[b][jq*4] =
                *(const float4*)&w0[b*WD + jt*64 + jq*4];
        }
        if (tid < 128) {
            int j = tid >> 1, cq = tid & 1;
            float4 v = *(const float4*)&mod_w[(size_t)(jt*64 + j)*CH + c0 + cq*4];
            mwsT[cq*4 + 0][j] = v.x;
            mwsT[cq*4 + 1][j] = v.y;
            mwsT[cq*4 + 2][j] = v.z;
            mwsT[cq*4 + 3][j] = v.w;
        }
        __syncthreads();
        #pragma unroll
        for (int j4 = 0; j4 < 16; j4++) {
            float4 mv = *(const float4*)&mwsT[c][j4*4];
            float4 a0 = *(const float4*)&w0s[bg*2    ][j4*4];
            float4 a1 = *(const float4*)&w0s[bg*2 + 1][j4*4];
            acc0 += a0.x*mv.x + a0.y*mv.y + a0.z*mv.z + a0.w*mv.w;
            acc1 += a1.x*mv.x + a1.y*mv.y + a1.z*mv.z + a1.w*mv.w;
        }
        __syncthreads();
    }
    const float inv = 1.0f / sqrtf((float)WD);
    float bb = mod_b[c0 + c] + 1.0f;
    float s0 = acc0*inv + bb;
    float s1 = acc1*inv + bb;
    int ch = c0 + c;
    g_sT[(size_t)ch*BATCH + bg*2    ] = s0;
    g_sT[(size_t)ch*BATCH + bg*2 + 1] = s1;
    g_s2[(size_t)(bg*2    )*CH + ch] = s0*s0;
    g_s2[(size_t)(bg*2 + 1)*CH + ch] = s1*s1;
}

// ---------------- Kernel B: fused modconv GEMM (split-K), raw partials out
// grid 256 = 128 n-tiles x 2 k-halves; 256 threads; thread tile 4m x 4n.
__global__ __launch_bounds__(256) void fused_kernel(
        const float* __restrict__ conv_w,    // [3,3,512,512] HWIO
        const float* __restrict__ cst) {     // [1,512,4,4]
    __shared__ float s_s[KC][BATCH];         // 16KB
    __shared__ float u_s[KC][TN + 4];        // 17KB

    const int tid = threadIdx.x;
    const int tx = tid & 15;                 // 4 n each
    const int ty = tid >> 4;                 // 0..15, 4 m each
    const int ntile = blockIdx.x >> 1;
    const int half  = blockIdx.x & 1;
    const int n0 = ntile * TN;
    const int o0 = n0 >> 4;
    const int kbase = half * KHALF;

    const int bi = tid >> 2;                 // U-build input channel (local)
    const int bo = tid & 3;                  // U-build output channel (local)

    const float coef = 1.0f / sqrtf(9.0f * (float)CH);

    F2 acc[2][4];
    #pragma unroll
    for (int a = 0; a < 2; a++)
        #pragma unroll
        for (int c = 0; c < 4; c++) { acc[a][c].f.x = 0.f; acc[a][c].f.y = 0.f; }

    // ---- prefetch tile 0 into regs ----
    float  w9[9];
    float4 c4[4];
    float4 s4[4];
    {
        const float* wp = conv_w + (size_t)(kbase + bi)*CH + o0 + bo;
        #pragma unroll
        for (int t = 0; t < 9; t++) w9[t] = wp[(size_t)t*CH*CH];
        const float4* cp = (const float4*)&cst[(kbase + bi)*NPIX];
        #pragma unroll
        for (int qd = 0; qd < 4; qd++) c4[qd] = cp[qd];
        #pragma unroll
        for (int j = 0; j < 4; j++) {
            int f = tid + j*256;
            int k = f >> 4, mq = f & 15;
            s4[j] = *(const float4*)&g_sT[(size_t)(kbase + k)*BATCH + mq*4];
        }
    }

    for (int kt = 0; kt < KHALF/KC; kt++) {
        __syncthreads();                     // A: prev GEMM done

        // stage s tile
        #pragma unroll
        for (int j = 0; j < 4; j++) {
            int f = tid + j*256;
            int k = f >> 4, mq = f & 15;
            *(float4*)&s_s[k][mq*4] = s4[j];
        }
        // build U row + write q to global
        {
            float q = 0.f, wr[9];
            #pragma unroll
            for (int t = 0; t < 9; t++) { float w = w9[t]*coef; wr[t] = w; q += w*w; }
            g_qT[(size_t)(kbase + kt*KC + bi)*CH + o0 + bo] = q;
            float c16[NPIX];
            *(float4*)&c16[0] = c4[0]; *(float4*)&c16[4] = c4[1];
            *(float4*)&c16[8] = c4[2]; *(float4*)&c16[12] = c4[3];
            #pragma unroll
            for (int h = 0; h < 4; h++) {
                float u4[4];
                #pragma unroll
                for (int x = 0; x < 4; x++) {
                    float a = 0.f;
                    #pragma unroll
                    for (int kh = 0; kh < 3; kh++) {
                        int hh = h + kh - 1;
                        if (hh < 0 || hh >= 4) continue;
                        #pragma unroll
                        for (int kw = 0; kw < 3; kw++) {
                            int xx = x + kw - 1;
                            if (xx < 0 || xx >= 4) continue;
                            a += wr[kh*3 + kw] * c16[hh*4 + xx];
                        }
                    }
                    u4[x] = a;
                }
                *(float4*)&u_s[bi][bo*NPIX + h*4] = *(float4*)&u4[0];
            }
        }

        // prefetch next tile (LDGs overlap barrier + GEMM)
        if (kt < KHALF/KC - 1) {
            const int kn = kbase + (kt + 1) * KC;
            const float* wp = conv_w + (size_t)(kn + bi)*CH + o0 + bo;
            #pragma unroll
            for (int t = 0; t < 9; t++) w9[t] = wp[(size_t)t*CH*CH];
            const float4* cp = (const float4*)&cst[(kn + bi)*NPIX];
            #pragma unroll
            for (int qd = 0; qd < 4; qd++) c4[qd] = cp[qd];
            #pragma unroll
            for (int j = 0; j < 4; j++) {
                int f = tid + j*256;
                int k = f >> 4, mq = f & 15;
                s4[j] = *(const float4*)&g_sT[(size_t)(kn + k)*BATCH + mq*4];
            }
        }

        __syncthreads();                     // B: tiles ready

        // GEMM: 4m x 4n per thread, m packed f32x2
        #pragma unroll 8
        for (int k = 0; k < KC; k++) {
            float4 sa = *(const float4*)&s_s[k][ty*4];
            float4 uv = *(const float4*)&u_s[k][tx*4];
            F2 p0, p1, u0, u1, u2, u3;
            p0.f = make_float2(sa.x, sa.y);
            p1.f = make_float2(sa.z, sa.w);
            u0.f = make_float2(uv.x, uv.x);
            u1.f = make_float2(uv.y, uv.y);
            u2.f = make_float2(uv.z, uv.z);
            u3.f = make_float2(uv.w, uv.w);
            fma2(acc[0][0], p0, u0); fma2(acc[0][1], p0, u1);
            fma2(acc[0][2], p0, u2); fma2(acc[0][3], p0, u3);
            fma2(acc[1][0], p1, u0); fma2(acc[1][1], p1, u1);
            fma2(acc[1][2], p1, u2); fma2(acc[1][3], p1, u3);
        }
    }

    // ---- store raw partials ----
    float* pb = g_part[half];
    #pragma unroll
    for (int a = 0; a < 4; a++) {
        int m = ty*4 + a;
        float4 v;
        v.x = (a & 1) ? acc[a>>1][0].f.y : acc[a>>1][0].f.x;
        v.y = (a & 1) ? acc[a>>1][1].f.y : acc[a>>1][1].f.x;
        v.z = (a & 1) ? acc[a>>1][2].f.y : acc[a>>1][2].f.x;
        v.w = (a & 1) ? acc[a>>1][3].f.y : acc[a>>1][3].f.x;
        *(float4*)&pb[(size_t)m*NCOL + n0 + tx*4] = v;
    }
}

// ---------------- Kernel C: demod  d[b,o] = rsqrt(sum_i s2[b,i]*q[i,o] + 1e-8)
// grid 64 (o-tile 8 each), 256 threads.
__global__ __launch_bounds__(256) void demod_kernel() {
    __shared__ float qT_s[CH][8];            // 16KB
    const int tid = threadIdx.x;
    const int o0 = blockIdx.x * 8;

    #pragma unroll
    for (int r = 0; r < 2; r++) {
        int i = tid + r*256;
        float4 a = *(const float4*)&g_qT[(size_t)i*CH + o0];
        float4 b = *(const float4*)&g_qT[(size_t)i*CH + o0 + 4];
        qT_s[i][0] = a.x; qT_s[i][1] = a.y; qT_s[i][2] = a.z; qT_s[i][3] = a.w;
        qT_s[i][4] = b.x; qT_s[i][5] = b.y; qT_s[i][6] = b.z; qT_s[i][7] = b.w;
    }
    __syncthreads();

    const int og = tid & 7;
    const int bg = tid >> 3;                 // 0..31, 2 b each
    #pragma unroll
    for (int h = 0; h < 2; h++) {
        int b = bg*2 + h;
        float acc = 1e-8f;
        const float4* sp = (const float4*)&g_s2[(size_t)b*CH];
        #pragma unroll 4
        for (int i4 = 0; i4 < CH/4; i4++) {
            float4 s2v = sp[i4];
            acc = fmaf(s2v.x, qT_s[i4*4+0][og], acc);
            acc = fmaf(s2v.y, qT_s[i4*4+1][og], acc);
            acc = fmaf(s2v.z, qT_s[i4*4+2][og], acc);
            acc = fmaf(s2v.w, qT_s[i4*4+3][og], acc);
        }
        g_d[(size_t)b*CH + o0 + og] = rsqrtf(acc);
    }
}

// ---------------- Kernel D: reduce partials + demod + noise + bias + lrelu
__global__ __launch_bounds__(256) void reduce_kernel(
        const float* __restrict__ noise,
        const float* __restrict__ ns_ptr,
        const float* __restrict__ bias,
        float* __restrict__ out) {
    const int gid = blockIdx.x * 256 + threadIdx.x;
    const int base = gid * 4;                // float4 granularity
    const int b = base >> 13;                // /8192
    const int n = base & (NCOL - 1);
    const int o = n >> 4;
    const int p = n & 15;

    float4 p0 = *(const float4*)&g_part[0][base];
    float4 p1 = *(const float4*)&g_part[1][base];
    float dv  = g_d[(size_t)b*CH + o];
    float4 nz = *(const float4*)&noise[b*NPIX + p];
    float bb  = bias[o];
    float ns  = ns_ptr[0];
    const float gain = 1.41421356237309515f;

    float4 r;
    float x;
    x = (p0.x + p1.x)*dv + nz.x*ns + bb; r.x = (x > 0.f ? x : 0.2f*x)*gain;
    x = (p0.y + p1.y)*dv + nz.y*ns + bb; r.y = (x > 0.f ? x : 0.2f*x)*gain;
    x = (p0.z + p1.z)*dv + nz.z*ns + bb; r.z = (x > 0.f ? x : 0.2f*x)*gain;
    x = (p0.w + p1.w)*dv + nz.w*ns + bb; r.w = (x > 0.f ? x : 0.2f*x)*gain;
    *(float4*)&out[base] = r;
}

extern "C" void kernel_launch(void* const* d_in, const int* in_sizes, int n_in,
                              void* d_out, int out_size) {
    const float* w0     = (const float*)d_in[0];
    const float* cst    = (const float*)d_in[1];
    const float* conv_w = (const float*)d_in[2];
    const float* mod_w  = (const float*)d_in[3];
    const float* mod_b  = (const float*)d_in[4];
    const float* noise  = (const float*)d_in[5];
    const float* nstr   = (const float*)d_in[6];
    const float* bias   = (const float*)d_in[7];
    float* out = (float*)d_out;

    style_kernel <<<64, 256>>>(w0, mod_w, mod_b);
    fused_kernel <<<256, 256>>>(conv_w, cst);
    demod_kernel <<<64, 256>>>();
    reduce_kernel<<<(BATCH*NCOL)/(256*4), 256>>>(noise, nstr, bias, out);
}

// round 9
// speedup vs baseline: 1.0322x; 1.0322x over previous
#include <cuda_runtime.h>
#include <math.h>

#define BATCH 64
#define CH 512
#define WD 512
#define NPIX 16
#define NCOL (CH*NPIX)   /* 8192 */
#define KC 64            /* k-tile */
#define TN 32            /* n-tile = 2 out-ch x 16 px */
#define TM 32            /* m-half per CTA */

// ---- scratch (allocation-free rule: __device__ global) ----
__device__ __align__(16) float g_sT[CH*BATCH];   // style transposed [i][b]

union F2 { float2 f; unsigned long long u; };
__device__ __forceinline__ void fma2(F2& d, F2 a, F2 b) {
    asm("fma.rn.f32x2 %0, %1, %2, %0;" : "+l"(d.u) : "l"(a.u), "l"(b.u));
}

// ---------------- Kernel A: style dense  s = w0 @ (mod_w/sqrt(512)) + mod_b + 1
__global__ __launch_bounds__(256) void style_kernel(
        const float* __restrict__ w0,
        const float* __restrict__ mod_w,
        const float* __restrict__ mod_b) {
    __shared__ float w0s[64][68];
    __shared__ float mwsT[8][68];
    const int tid = threadIdx.x;
    const int c  = tid & 7;
    const int bg = tid >> 3;         // 0..31 (2 b each)
    const int c0 = blockIdx.x * 8;

    float acc0 = 0.f, acc1 = 0.f;

    for (int jt = 0; jt < 8; jt++) {
        #pragma unroll
        for (int q = 0; q < 4; q++) {
            int f = tid + q*256;
            int b = f >> 4, jq = f & 15;
            *(float4*)&w0s[b][jq*4] =
                *(const float4*)&w0[b*WD + jt*64 + jq*4];
        }
        if (tid < 128) {
            int j = tid >> 1, cq = tid & 1;
            float4 v = *(const float4*)&mod_w[(size_t)(jt*64 + j)*CH + c0 + cq*4];
            mwsT[cq*4 + 0][j] = v.x;
            mwsT[cq*4 + 1][j] = v.y;
            mwsT[cq*4 + 2][j] = v.z;
            mwsT[cq*4 + 3][j] = v.w;
        }
        __syncthreads();
        #pragma unroll
        for (int j4 = 0; j4 < 16; j4++) {
            float4 mv = *(const float4*)&mwsT[c][j4*4];
            float4 a0 = *(const float4*)&w0s[bg*2    ][j4*4];
            float4 a1 = *(const float4*)&w0s[bg*2 + 1][j4*4];
            acc0 += a0.x*mv.x + a0.y*mv.y + a0.z*mv.z + a0.w*mv.w;
            acc1 += a1.x*mv.x + a1.y*mv.y + a1.z*mv.z + a1.w*mv.w;
        }
        __syncthreads();
    }
    const float inv = 1.0f / sqrtf((float)WD);
    float bb = mod_b[c0 + c] + 1.0f;
    int ch = c0 + c;
    g_sT[(size_t)ch*BATCH + bg*2    ] = acc0*inv + bb;
    g_sT[(size_t)ch*BATCH + bg*2 + 1] = acc1*inv + bb;
}

// ---------------- Kernel B: fused modconv
// grid 512 = 256 n-tiles x 2 m-halves; 128 threads; thread tile 4m x 2n (f32x2 m-pairs).
// U built in regs from prefetched global loads; demod 2-warp side-loop; 2 barriers/tile.
__global__ __launch_bounds__(128) void fused_kernel(
        const float* __restrict__ conv_w,    // [3,3,512,512] HWIO
        const float* __restrict__ cst,       // [1,512,4,4]
        const float* __restrict__ noise,     // [B,1,4,4]
        const float* __restrict__ ns_ptr,    // scalar
        const float* __restrict__ bias,      // [C]
        float* __restrict__ out) {           // [B,C,4,4]
    __shared__ float s_s[KC][TM];            // s tile [k][m]     8KB
    __shared__ float u_s[KC][TN + 4];        // U tile (padded)   9KB
    __shared__ float q_s[KC][2];             // q[k][og]          512B
    __shared__ float d_s[2][TM];             // demod factors     256B

    const int tid = threadIdx.x;
    const int tx = tid & 15;                 // n-group (2 cols)
    const int ty = tid >> 4;                 // 0..7, m-group (4 rows)
    const int ntile = blockIdx.x >> 1;
    const int m0 = (blockIdx.x & 1) * TM;
    const int n0 = ntile * TN;
    const int o0 = n0 >> 4;                  // first of 2 output channels

    const int bi = tid >> 1;                 // U-build input channel (local) 0..63
    const int bo = tid & 1;                  // U-build output channel 0..1

    const float coef = 1.0f / sqrtf(9.0f * (float)CH);

    F2 acc[2][2];                            // [m-pair][n]
    #pragma unroll
    for (int a = 0; a < 2; a++)
        #pragma unroll
        for (int c = 0; c < 2; c++) { acc[a][c].f.x = 0.f; acc[a][c].f.y = 0.f; }
    float acc2 = 0.f;

    // ---- prefetch tile 0 into regs ----
    float  w9[9];
    float4 c4[4];
    float4 s4[4];
    const float* wp = conv_w + (size_t)bi*CH + o0 + bo;
    const float4* cp = (const float4*)&cst[bi*NPIX];
    {
        #pragma unroll
        for (int t = 0; t < 9; t++) w9[t] = wp[(size_t)t*CH*CH];
        #pragma unroll
        for (int qd = 0; qd < 4; qd++) c4[qd] = cp[qd];
        #pragma unroll
        for (int j = 0; j < 4; j++) {
            int f = tid + j*128;
            int k = f >> 3, mq = f & 7;
            s4[j] = *(const float4*)&g_sT[(size_t)k*BATCH + m0 + mq*4];
        }
    }

    for (int kt = 0; kt < CH/KC; kt++) {
        __syncthreads();                     // A: prev GEMM + side-loop done

        // stage s tile
        #pragma unroll
        for (int j = 0; j < 4; j++) {
            int f = tid + j*128;
            int k = f >> 3, mq = f & 7;
            *(float4*)&s_s[k][mq*4] = s4[j];
        }
        // build U row + q into smem
        {
            float q = 0.f, wr[9];
            #pragma unroll
            for (int t = 0; t < 9; t++) { float w = w9[t]*coef; wr[t] = w; q += w*w; }
            q_s[bi][bo] = q;
            float c16[NPIX];
            *(float4*)&c16[0] = c4[0]; *(float4*)&c16[4] = c4[1];
            *(float4*)&c16[8] = c4[2]; *(float4*)&c16[12] = c4[3];
            #pragma unroll
            for (int h = 0; h < 4; h++) {
                float u4[4];
                #pragma unroll
                for (int x = 0; x < 4; x++) {
                    float a = 0.f;
                    #pragma unroll
                    for (int kh = 0; kh < 3; kh++) {
                        int hh = h + kh - 1;
                        if (hh < 0 || hh >= 4) continue;
                        #pragma unroll
                        for (int kw = 0; kw < 3; kw++) {
                            int xx = x + kw - 1;
                            if (xx < 0 || xx >= 4) continue;
                            a += wr[kh*3 + kw] * c16[hh*4 + xx];
                        }
                    }
                    u4[x] = a;
                }
                *(float4*)&u_s[bi][bo*NPIX + h*4] = *(float4*)&u4[0];
            }
        }

        // prefetch next tile (LDGs overlap barrier + GEMM)
        if (kt < CH/KC - 1) {
            const int kn = (kt + 1) * KC;
            const float* wpn = wp + (size_t)kn*CH;
            #pragma unroll
            for (int t = 0; t < 9; t++) w9[t] = wpn[(size_t)t*CH*CH];
            const float4* cpn = cp + kn*(NPIX/4);
            #pragma unroll
            for (int qd = 0; qd < 4; qd++) c4[qd] = cpn[qd];
            #pragma unroll
            for (int j = 0; j < 4; j++) {
                int f = tid + j*128;
                int k = f >> 3, mq = f & 7;
                s4[j] = *(const float4*)&g_sT[(size_t)(kn + k)*BATCH + m0 + mq*4];
            }
        }

        __syncthreads();                     // B: tiles ready

        // GEMM: 4m x 2n per thread, m packed f32x2
        #pragma unroll 8
        for (int k = 0; k < KC; k++) {
            float4 sa = *(const float4*)&s_s[k][ty*4];
            float2 u2 = *(const float2*)&u_s[k][tx*2];
            F2 p0, p1, u0, u1;
            p0.f = make_float2(sa.x, sa.y);
            p1.f = make_float2(sa.z, sa.w);
            u0.f = make_float2(u2.x, u2.x);
            u1.f = make_float2(u2.y, u2.y);
            fma2(acc[0][0], p0, u0); fma2(acc[0][1], p0, u1);
            fma2(acc[1][0], p1, u0); fma2(acc[1][1], p1, u1);
        }

        // demod side-loop: 2 warps, one (m, og) per thread
        if (tid < 64) {
            int dm = tid & 31, dg = tid >> 5;
            float a2 = 0.f;
            #pragma unroll 8
            for (int k = 0; k < KC; k++) {
                float sv = s_s[k][dm];
                a2 = fmaf(sv*sv, q_s[k][dg], a2);
            }
            acc2 += a2;
        }
    }

    __syncthreads();
    if (tid < 64)
        d_s[tid >> 5][tid & 31] = rsqrtf(acc2 + 1e-8f);
    __syncthreads();

    // ---- epilogue: demod, noise, bias, leaky-relu * sqrt(2) ----
    const float nstr = ns_ptr[0];
    const int ol = tx >> 3;                  // local out-channel 0..1
    const float bb = bias[o0 + ol];
    const int px = (tx*2) & 15;
    const float gain = 1.41421356237309515f;
    #pragma unroll
    for (int mp = 0; mp < 2; mp++) {
        #pragma unroll
        for (int h = 0; h < 2; h++) {
            int ml = ty*4 + mp*2 + h;
            int b  = m0 + ml;
            float dv = d_s[ol][ml];
            float2 nz = *(const float2*)&noise[b*NPIX + px];
            float x0 = (h ? acc[mp][0].f.y : acc[mp][0].f.x) * dv + nz.x*nstr + bb;
            float x1 = (h ? acc[mp][1].f.y : acc[mp][1].f.x) * dv + nz.y*nstr + bb;
            x0 = (x0 > 0.f ? x0 : 0.2f*x0) * gain;
            x1 = (x1 > 0.f ? x1 : 0.2f*x1) * gain;
            *(float2*)&out[(size_t)b*NCOL + n0 + tx*2] = make_float2(x0, x1);
        }
    }
}

extern "C" void kernel_launch(void* const* d_in, const int* in_sizes, int n_in,
                              void* d_out, int out_size) {
    const float* w0     = (const float*)d_in[0];
    const float* cst    = (const float*)d_in[1];
    const float* conv_w = (const float*)d_in[2];
    const float* mod_w  = (const float*)d_in[3];
    const float* mod_b  = (const float*)d_in[4];
    const float* noise  = (const float*)d_in[5];
    const float* nstr   = (const float*)d_in[6];
    const float* bias   = (const float*)d_in[7];
    float* out = (float*)d_out;

    style_kernel<<<64, 256>>>(w0, mod_w, mod_b);
    fused_kernel<<<(NCOL / TN) * 2, 128>>>(conv_w, cst, noise, nstr, bias, out);
}

// round 11
// speedup vs baseline: 1.0946x; 1.0604x over previous
#include <cuda_runtime.h>
#include <cuda_bf16.h>
#include <math.h>

typedef unsigned int u32;

#define BATCH 64
#define CH 512
#define WD 512
#define NPIX 16
#define NCOL (CH*NPIX)   /* 8192 */
#define TN 64            /* n-tile = 4 out-ch x 16 px */
#define KCH 64           /* k per chunk */
#define NCHUNK (CH/KCH)  /* 8 */
#define APAD 72          /* padded row length (144B, 16B-aligned) */

// ---- scratch (allocation-free rule: __device__ globals) ----
__device__ __align__(16) float g_s2[BATCH*CH];            // s^2 [b][k]
__device__ __align__(16) __nv_bfloat16 g_Sh[BATCH*CH];    // s hi [m][k]
__device__ __align__(16) __nv_bfloat16 g_Sl[BATCH*CH];    // s lo [m][k]
__device__ __align__(16) float g_d[BATCH*CH];             // demod [b][o]

// ---- warp-MMA helpers (sm_80-era ISA; valid in compute_100 PTX) ----
__device__ __forceinline__ u32 smem_u32(const void* p) {
    u32 a;
    asm("{ .reg .u64 t; cvta.to.shared.u64 t, %1; cvt.u32.u64 %0, t; }" : "=r"(a) : "l"(p));
    return a;
}
__device__ __forceinline__ void ldsm_x4(u32* r, u32 addr) {
    asm volatile("ldmatrix.sync.aligned.m8n8.x4.shared.b16 {%0,%1,%2,%3}, [%4];"
        : "=r"(r[0]), "=r"(r[1]), "=r"(r[2]), "=r"(r[3]) : "r"(addr));
}
__device__ __forceinline__ void ldsm_x2(u32* r, u32 addr) {
    asm volatile("ldmatrix.sync.aligned.m8n8.x2.shared.b16 {%0,%1}, [%2];"
        : "=r"(r[0]), "=r"(r[1]) : "r"(addr));
}
__device__ __forceinline__ void mma16816(float* c, const u32* a, const u32* b) {
    asm volatile("mma.sync.aligned.m16n8k16.row.col.f32.bf16.bf16.f32 "
        "{%0,%1,%2,%3}, {%4,%5,%6,%7}, {%8,%9}, {%0,%1,%2,%3};"
        : "+f"(c[0]), "+f"(c[1]), "+f"(c[2]), "+f"(c[3])
        : "r"(a[0]), "r"(a[1]), "r"(a[2]), "r"(a[3]), "r"(b[0]), "r"(b[1]));
}

// ============== Kernel A: style dense + hi/lo bf16 split + s^2 ==============
__global__ __launch_bounds__(256) void style_kernel(
        const float* __restrict__ w0,
        const float* __restrict__ mod_w,
        const float* __restrict__ mod_b) {
    __shared__ float w0s[64][68];
    __shared__ float mwsT[8][68];
    const int tid = threadIdx.x;
    const int c  = tid & 7;
    const int bg = tid >> 3;
    const int c0 = blockIdx.x * 8;

    float acc0 = 0.f, acc1 = 0.f;
    for (int jt = 0; jt < 8; jt++) {
        #pragma unroll
        for (int q = 0; q < 4; q++) {
            int f = tid + q*256;
            int b = f >> 4, jq = f & 15;
            *(float4*)&w0s[b][jq*4] = *(const float4*)&w0[b*WD + jt*64 + jq*4];
        }
        if (tid < 128) {
            int j = tid >> 1, cq = tid & 1;
            float4 v = *(const float4*)&mod_w[(size_t)(jt*64 + j)*CH + c0 + cq*4];
            mwsT[cq*4 + 0][j] = v.x; mwsT[cq*4 + 1][j] = v.y;
            mwsT[cq*4 + 2][j] = v.z; mwsT[cq*4 + 3][j] = v.w;
        }
        __syncthreads();
        #pragma unroll
        for (int j4 = 0; j4 < 16; j4++) {
            float4 mv = *(const float4*)&mwsT[c][j4*4];
            float4 a0 = *(const float4*)&w0s[bg*2    ][j4*4];
            float4 a1 = *(const float4*)&w0s[bg*2 + 1][j4*4];
            acc0 += a0.x*mv.x + a0.y*mv.y + a0.z*mv.z + a0.w*mv.w;
            acc1 += a1.x*mv.x + a1.y*mv.y + a1.z*mv.z + a1.w*mv.w;
        }
        __syncthreads();
    }
    const float inv = 1.0f / sqrtf((float)WD);
    float bb = mod_b[c0 + c] + 1.0f;
    float s0 = acc0*inv + bb;
    float s1 = acc1*inv + bb;
    int k = c0 + c;
    int b0 = bg*2, b1 = bg*2 + 1;
    g_s2[(size_t)b0*CH + k] = s0*s0;
    g_s2[(size_t)b1*CH + k] = s1*s1;
    __nv_bfloat16 h0 = __float2bfloat16(s0);
    __nv_bfloat16 h1 = __float2bfloat16(s1);
    g_Sh[(size_t)b0*CH + k] = h0;
    g_Sh[(size_t)b1*CH + k] = h1;
    g_Sl[(size_t)b0*CH + k] = __float2bfloat16(s0 - __bfloat162float(h0));
    g_Sl[(size_t)b1*CH + k] = __float2bfloat16(s1 - __bfloat162float(h1));
}

// ============== Kernel B: demod (exact fp32) ==============
__global__ __launch_bounds__(512) void demod_kernel(const float* __restrict__ conv_w) {
    __shared__ float q_s[CH][9];
    const int tid = threadIdx.x;
    const int o0 = blockIdx.x * 8;
    const float c2 = 1.0f / (9.0f * (float)CH);

    {
        int i = tid;
        float q8[8];
        #pragma unroll
        for (int o = 0; o < 8; o++) q8[o] = 0.f;
        #pragma unroll
        for (int t = 0; t < 9; t++) {
            const float* p = conv_w + (size_t)t*CH*CH + (size_t)i*CH + o0;
            float4 a = *(const float4*)p;
            float4 b = *(const float4*)(p + 4);
            q8[0] += a.x*a.x; q8[1] += a.y*a.y; q8[2] += a.z*a.z; q8[3] += a.w*a.w;
            q8[4] += b.x*b.x; q8[5] += b.y*b.y; q8[6] += b.z*b.z; q8[7] += b.w*b.w;
        }
        #pragma unroll
        for (int o = 0; o < 8; o++) q_s[i][o] = q8[o] * c2;
    }
    __syncthreads();

    const int b  = tid >> 3;
    const int og = tid & 7;
    float acc = 1e-8f;
    const float4* sp = (const float4*)&g_s2[(size_t)b*CH];
    #pragma unroll 4
    for (int i4 = 0; i4 < CH/4; i4++) {
        float4 s2v = sp[i4];
        acc = fmaf(s2v.x, q_s[i4*4+0][og], acc);
        acc = fmaf(s2v.y, q_s[i4*4+1][og], acc);
        acc = fmaf(s2v.z, q_s[i4*4+2][og], acc);
        acc = fmaf(s2v.w, q_s[i4*4+3][og], acc);
    }
    g_d[(size_t)b*CH + o0 + og] = rsqrtf(acc);
}

// ============== Kernel C: mma.sync main GEMM ==============
// grid 128 n-tiles of 64; 128 threads = 4 warps (2m x 2n).
// y = Ah*Bh + Ah*Bl + Al*Bh (hi/lo bf16 split), fp32 accum.
__global__ __launch_bounds__(128) void mma_kernel(
        const float* __restrict__ conv_w,
        const float* __restrict__ cst,
        const float* __restrict__ noise,
        const float* __restrict__ ns_ptr,
        const float* __restrict__ bias,
        float* __restrict__ out) {
    __shared__ __align__(16) __nv_bfloat16 sAh[64*APAD];
    __shared__ __align__(16) __nv_bfloat16 sAl[64*APAD];
    __shared__ __align__(16) __nv_bfloat16 sBh[64*APAD];
    __shared__ __align__(16) __nv_bfloat16 sBl[64*APAD];

    const int tid = threadIdx.x;
    const int wid = tid >> 5;
    const int lane = tid & 31;
    const int wm = wid >> 1;                 // warp m-half 0..1
    const int wn = wid & 1;                  // warp n-half 0..1
    const int n0 = blockIdx.x * TN;
    const int o0 = n0 >> 4;

    const u32 ah_base = smem_u32(sAh);
    const u32 al_base = smem_u32(sAl);
    const u32 bh_base = smem_u32(sBh);
    const u32 bl_base = smem_u32(sBl);

    // lane-dependent ldmatrix base offsets (bytes)
    const u32 aRow = (u32)(wm*32 + (lane & 15));
    const u32 aCol = (u32)(((lane >> 4) & 1) * 8);
    const u32 aOff = aRow*(APAD*2) + aCol*2;
    const u32 bRow = (u32)(wn*32 + (lane & 7));
    const u32 bCol = (u32)(((lane >> 3) & 1) * 8);
    const u32 bOff = bRow*(APAD*2) + bCol*2;

    const int bi = tid >> 1;                 // U-build input channel 0..63
    const int oh = tid & 1;                  // U-build o-pair selector
    const float coef = 1.0f / sqrtf(9.0f * (float)CH);

    float acc[2][4][4];
    #pragma unroll
    for (int mf = 0; mf < 2; mf++)
        #pragma unroll
        for (int nf = 0; nf < 4; nf++)
            #pragma unroll
            for (int e = 0; e < 4; e++) acc[mf][nf][e] = 0.f;

    for (int ck = 0; ck < NCHUNK; ck++) {
        const int k0 = ck * KCH;
        __syncthreads();                     // prev MMA done; buffers free

        // ---- stage A hi/lo (64m x 64k bf16 each) ----
        #pragma unroll
        for (int j = 0; j < 4; j++) {
            int idx = tid + j*128;           // 0..511
            int m = idx >> 3, k8 = idx & 7;
            *(uint4*)&sAh[m*APAD + k8*8] =
                ((const uint4*)(g_Sh + (size_t)m*CH + k0))[k8];
            *(uint4*)&sAl[m*APAD + k8*8] =
                ((const uint4*)(g_Sl + (size_t)m*CH + k0))[k8];
        }

        // ---- build B = U tile: [n][k], hi/lo ----
        {
            float c16[NPIX];
            const float4* cp = (const float4*)&cst[(k0 + bi)*NPIX];
            *(float4*)&c16[0]  = cp[0]; *(float4*)&c16[4]  = cp[1];
            *(float4*)&c16[8]  = cp[2]; *(float4*)&c16[12] = cp[3];
            #pragma unroll
            for (int oo = 0; oo < 2; oo++) {
                const int ol = oh*2 + oo;
                float wr[9];
                #pragma unroll
                for (int t = 0; t < 9; t++)
                    wr[t] = conv_w[(size_t)t*CH*CH + (size_t)(k0 + bi)*CH + o0 + ol] * coef;
                #pragma unroll
                for (int h = 0; h < 4; h++) {
                    #pragma unroll
                    for (int x = 0; x < 4; x++) {
                        float a = 0.f;
                        #pragma unroll
                        for (int kh = 0; kh < 3; kh++) {
                            int hh = h + kh - 1;
                            if (hh < 0 || hh >= 4) continue;
                            #pragma unroll
                            for (int kw = 0; kw < 3; kw++) {
                                int xx = x + kw - 1;
                                if (xx < 0 || xx >= 4) continue;
                                a += wr[kh*3 + kw] * c16[hh*4 + xx];
                            }
                        }
                        int n = ol*NPIX + h*4 + x;
                        __nv_bfloat16 hv = __float2bfloat16(a);
                        sBh[n*APAD + bi] = hv;
                        sBl[n*APAD + bi] = __float2bfloat16(a - __bfloat162float(hv));
                    }
                }
            }
        }
        __syncthreads();                     // tiles ready

        // ---- MMA: 4 k-steps x (2 mf x 4 nf) x 3 passes ----
        #pragma unroll
        for (int ks = 0; ks < 4; ks++) {
            const u32 kb = (u32)(ks*16*2);   // bytes along k
            u32 ah[2][4], al[2][4];
            ldsm_x4(ah[0], ah_base + aOff + kb);
            ldsm_x4(ah[1], ah_base + aOff + 16*(APAD*2) + kb);
            ldsm_x4(al[0], al_base + aOff + kb);
            ldsm_x4(al[1], al_base + aOff + 16*(APAD*2) + kb);
            #pragma unroll
            for (int nf = 0; nf < 4; nf++) {
                u32 bh[2], bl[2];
                const u32 nb = (u32)(nf*8*(APAD*2));
                ldsm_x2(bh, bh_base + bOff + nb + kb);
                ldsm_x2(bl, bl_base + bOff + nb + kb);
                #pragma unroll
                for (int mf = 0; mf < 2; mf++) {
                    mma16816(acc[mf][nf], ah[mf], bh);
                    mma16816(acc[mf][nf], ah[mf], bl);
                    mma16816(acc[mf][nf], al[mf], bh);
                }
            }
        }
    }
    __syncthreads();

    // ---- stage epilogue data into smem (reuse sAh as float buffer) ----
    float* ep = (float*)sAh;                 // [0..255] d, [256..1279] noise, [1280..1283] bias, [1284] nstr
    {
        #pragma unroll
        for (int j = 0; j < 2; j++) {
            int idx = tid + j*128;           // 0..255 : og*64 + b
            int og = idx >> 6, b = idx & 63;
            ep[idx] = g_d[(size_t)b*CH + o0 + og];
        }
        #pragma unroll
        for (int j = 0; j < 2; j++) {
            int idx = tid + j*128;           // 256 float4 of noise
            ((float4*)(ep + 256))[idx] = ((const float4*)noise)[idx];
        }
        if (tid < 4) ep[1280 + tid] = bias[o0 + tid];
        if (tid == 4) ep[1284] = ns_ptr[0];
    }
    __syncthreads();

    // ---- epilogue: demod, noise, bias, leaky-relu * sqrt(2) ----
    const float gain = 1.41421356237309515f;
    const float nstr = ep[1284];
    #pragma unroll
    for (int mf = 0; mf < 2; mf++) {
        #pragma unroll
        for (int nf = 0; nf < 4; nf++) {
            int row0 = wm*32 + mf*16 + (lane >> 2);
            int colb = wn*32 + nf*8 + 2*(lane & 3);
            int ol = colb >> 4;
            int px = colb & 15;
            float bb = ep[1280 + ol];
            #pragma unroll
            for (int hh = 0; hh < 2; hh++) {
                int b = row0 + hh*8;
                float dv = ep[ol*64 + b];
                float2 nz = *(const float2*)&ep[256 + b*NPIX + px];
                float x0 = acc[mf][nf][hh*2 + 0] * dv + nz.x*nstr + bb;
                float x1 = acc[mf][nf][hh*2 + 1] * dv + nz.y*nstr + bb;
                x0 = (x0 > 0.f ? x0 : 0.2f*x0) * gain;
                x1 = (x1 > 0.f ? x1 : 0.2f*x1) * gain;
                *(float2*)&out[(size_t)b*NCOL + n0 + colb] = make_float2(x0, x1);
            }
        }
    }
}

extern "C" void kernel_launch(void* const* d_in, const int* in_sizes, int n_in,
                              void* d_out, int out_size) {
    const float* w0     = (const float*)d_in[0];
    const float* cst    = (const float*)d_in[1];
    const float* conv_w = (const float*)d_in[2];
    const float* mod_w  = (const float*)d_in[3];
    const float* mod_b  = (const float*)d_in[4];
    const float* noise  = (const float*)d_in[5];
    const float* nstr   = (const float*)d_in[6];
    const float* bias   = (const float*)d_in[7];
    float* out = (float*)d_out;

    style_kernel<<<64, 256>>>(w0, mod_w, mod_b);
    demod_kernel<<<64, 512>>>(conv_w);
    mma_kernel<<<NCOL / TN, 128>>>(conv_w, cst, noise, nstr, bias, out);
}

// round 12
// speedup vs baseline: 1.1442x; 1.0453x over previous
#include <cuda_runtime.h>
#include <cuda_bf16.h>
#include <math.h>

typedef unsigned int u32;

#define BATCH 64
#define CH 512
#define WD 512
#define NPIX 16
#define NCOL (CH*NPIX)   /* 8192 */
#define TN 64            /* n-tile = 4 out-ch x 16 px */
#define KCH 64           /* k per chunk */
#define NCHUNK (CH/KCH)  /* 8 */
#define APAD 72          /* padded row (144B) */

// ---- scratch (allocation-free rule: __device__ globals) ----
__device__ __align__(16) float g_s2[BATCH*CH];            // s^2 [b][k]
__device__ __align__(16) __nv_bfloat16 g_Sh[BATCH*CH];    // s hi [m][k]
__device__ __align__(16) __nv_bfloat16 g_Sl[BATCH*CH];    // s lo [m][k]

// ---- warp-MMA helpers (sm_80-era ISA; valid in compute_100 PTX) ----
__device__ __forceinline__ u32 smem_u32(const void* p) {
    u32 a;
    asm("{ .reg .u64 t; cvta.to.shared.u64 t, %1; cvt.u32.u64 %0, t; }" : "=r"(a) : "l"(p));
    return a;
}
__device__ __forceinline__ void ldsm_x4(u32* r, u32 addr) {
    asm volatile("ldmatrix.sync.aligned.m8n8.x4.shared.b16 {%0,%1,%2,%3}, [%4];"
        : "=r"(r[0]), "=r"(r[1]), "=r"(r[2]), "=r"(r[3]) : "r"(addr));
}
__device__ __forceinline__ void ldsm_x2(u32* r, u32 addr) {
    asm volatile("ldmatrix.sync.aligned.m8n8.x2.shared.b16 {%0,%1}, [%2];"
        : "=r"(r[0]), "=r"(r[1]) : "r"(addr));
}
__device__ __forceinline__ void mma16816(float* c, const u32* a, const u32* b) {
    asm volatile("mma.sync.aligned.m16n8k16.row.col.f32.bf16.bf16.f32 "
        "{%0,%1,%2,%3}, {%4,%5,%6,%7}, {%8,%9}, {%0,%1,%2,%3};"
        : "+f"(c[0]), "+f"(c[1]), "+f"(c[2]), "+f"(c[3])
        : "r"(a[0]), "r"(a[1]), "r"(a[2]), "r"(a[3]), "r"(b[0]), "r"(b[1]));
}

// ============== Kernel A: style dense + hi/lo bf16 split + s^2 ==============
// grid 64 (8 c-cols each); 256 threads = 64 b x 4 c-pairs (each thread: c, c+4).
__global__ __launch_bounds__(256) void style_kernel(
        const float* __restrict__ w0,
        const float* __restrict__ mod_w,
        const float* __restrict__ mod_b) {
    __shared__ float w0s[64][68];    // [b][k] padded
    __shared__ float mwsT[8][68];    // [c][k] transposed, padded
    const int tid = threadIdx.x;
    const int b   = tid >> 2;        // 0..63
    const int cl  = tid & 3;         // handles cl and cl+4
    const int c0  = blockIdx.x * 8;

    float acc0 = 0.f, acc1 = 0.f;

    for (int kt = 0; kt < 8; kt++) {
        #pragma unroll
        for (int q = 0; q < 4; q++) {        // w0 tile 64x64 (1024 float4)
            int idx = tid + q*256;
            int m = idx >> 4, k4 = idx & 15;
            *(float4*)&w0s[m][k4*4] =
                *(const float4*)&w0[m*WD + kt*64 + k4*4];
        }
        if (tid < 128) {                     // mod_w tile 64k x 8c, transposed
            int k = tid >> 1, hf = tid & 1;
            float4 v = *(const float4*)&mod_w[(size_t)(kt*64 + k)*CH + c0 + hf*4];
            mwsT[hf*4 + 0][k] = v.x;
            mwsT[hf*4 + 1][k] = v.y;
            mwsT[hf*4 + 2][k] = v.z;
            mwsT[hf*4 + 3][k] = v.w;
        }
        __syncthreads();
        #pragma unroll
        for (int k4 = 0; k4 < 16; k4++) {
            float4 a  = *(const float4*)&w0s[b][k4*4];
            float4 m0 = *(const float4*)&mwsT[cl    ][k4*4];
            float4 m1 = *(const float4*)&mwsT[cl + 4][k4*4];
            acc0 += a.x*m0.x + a.y*m0.y + a.z*m0.z + a.w*m0.w;
            acc1 += a.x*m1.x + a.y*m1.y + a.z*m1.z + a.w*m1.w;
        }
        __syncthreads();
    }
    const float inv = 1.0f / sqrtf((float)WD);
    #pragma unroll
    for (int hf = 0; hf < 2; hf++) {
        int c = c0 + cl + hf*4;
        float s = (hf ? acc1 : acc0)*inv + mod_b[c] + 1.0f;
        g_s2[(size_t)b*CH + c] = s*s;
        __nv_bfloat16 h = __float2bfloat16(s);
        g_Sh[(size_t)b*CH + c] = h;
        g_Sl[(size_t)b*CH + c] = __float2bfloat16(s - __bfloat162float(h));
    }
}

// ============== Kernel B: mma.sync GEMM + fused demod + epilogue ==============
// grid 128 n-tiles of 64; 256 threads = 8 warps (2m x 4n).
// y = Ah*Bh + Ah*Bl + Al*Bh (hi/lo bf16 split), fp32 accum.
__global__ __launch_bounds__(256) void mma_kernel(
        const float* __restrict__ conv_w,
        const float* __restrict__ cst,
        const float* __restrict__ noise,
        const float* __restrict__ ns_ptr,
        const float* __restrict__ bias,
        float* __restrict__ out) {
    __shared__ __align__(16) __nv_bfloat16 sAh[64*APAD];
    __shared__ __align__(16) __nv_bfloat16 sAl[64*APAD];
    __shared__ __align__(16) __nv_bfloat16 sBh[64*APAD];
    __shared__ __align__(16) __nv_bfloat16 sBl[64*APAD];
    __shared__ __align__(16) float q_s[CH][4];   // q[k][ol]; reused as noise buf
    __shared__ float d_s[4][BATCH];
    __shared__ float bias_s[4];
    __shared__ float nstr_s;

    const int tid = threadIdx.x;
    const int wid = tid >> 5;
    const int lane = tid & 31;
    const int wm = wid >> 2;                 // m-half (32 rows)
    const int wn = wid & 3;                  // n-quarter (16 cols)
    const int n0 = blockIdx.x * TN;
    const int o0 = n0 >> 4;

    const u32 ah_base = smem_u32(sAh);
    const u32 al_base = smem_u32(sAl);
    const u32 bh_base = smem_u32(sBh);
    const u32 bl_base = smem_u32(sBl);

    const u32 aOff = (u32)(wm*32 + (lane & 15))*(APAD*2) + (u32)(((lane >> 4) & 1)*8)*2;
    const u32 bOff = (u32)(wn*16 + (lane & 7))*(APAD*2) + (u32)(((lane >> 3) & 1)*8)*2;

    const int bi = tid >> 2;                 // U-build input channel 0..63
    const int ol = tid & 3;                  // U-build local out channel 0..3
    const float coef = 1.0f / sqrtf(9.0f * (float)CH);

    float acc[2][2][4];
    #pragma unroll
    for (int mf = 0; mf < 2; mf++)
        #pragma unroll
        for (int nf = 0; nf < 2; nf++)
            #pragma unroll
            for (int e = 0; e < 4; e++) acc[mf][nf][e] = 0.f;

    // ---- prefetch chunk 0 into regs ----
    uint4 ah4[2], al4[2];
    float w9[9];
    float4 c4[4];
    {
        #pragma unroll
        for (int j = 0; j < 2; j++) {
            int idx = tid + j*256;
            int m = idx >> 3, k8 = idx & 7;
            ah4[j] = ((const uint4*)(g_Sh + (size_t)m*CH))[k8];
            al4[j] = ((const uint4*)(g_Sl + (size_t)m*CH))[k8];
        }
        #pragma unroll
        for (int t = 0; t < 9; t++)
            w9[t] = conv_w[(size_t)t*CH*CH + (size_t)bi*CH + o0 + ol];
        const float4* cp = (const float4*)&cst[bi*NPIX];
        #pragma unroll
        for (int qd = 0; qd < 4; qd++) c4[qd] = cp[qd];
    }

    for (int ck = 0; ck < NCHUNK; ck++) {
        const int k0 = ck * KCH;
        __syncthreads();                     // A: buffers free

        // ---- store A tiles ----
        #pragma unroll
        for (int j = 0; j < 2; j++) {
            int idx = tid + j*256;
            int m = idx >> 3, k8 = idx & 7;
            *(uint4*)&sAh[m*APAD + k8*8] = ah4[j];
            *(uint4*)&sAl[m*APAD + k8*8] = al4[j];
        }
        // ---- build B tile + q ----
        {
            float wr[9], q = 0.f;
            #pragma unroll
            for (int t = 0; t < 9; t++) { float w = w9[t]*coef; wr[t] = w; q += w*w; }
            q_s[k0 + bi][ol] = q;
            float c16[NPIX];
            *(float4*)&c16[0]  = c4[0]; *(float4*)&c16[4]  = c4[1];
            *(float4*)&c16[8]  = c4[2]; *(float4*)&c16[12] = c4[3];
            #pragma unroll
            for (int h = 0; h < 4; h++) {
                #pragma unroll
                for (int x = 0; x < 4; x++) {
                    float a = 0.f;
                    #pragma unroll
                    for (int kh = 0; kh < 3; kh++) {
                        int hh = h + kh - 1;
                        if (hh < 0 || hh >= 4) continue;
                        #pragma unroll
                        for (int kw = 0; kw < 3; kw++) {
                            int xx = x + kw - 1;
                            if (xx < 0 || xx >= 4) continue;
                            a += wr[kh*3 + kw] * c16[hh*4 + xx];
                        }
                    }
                    int n = ol*NPIX + h*4 + x;
                    __nv_bfloat16 hv = __float2bfloat16(a);
                    sBh[n*APAD + bi] = hv;
                    sBl[n*APAD + bi] = __float2bfloat16(a - __bfloat162float(hv));
                }
            }
        }
        // ---- prefetch next chunk (LDGs land during MMA) ----
        if (ck < NCHUNK - 1) {
            const int kn = k0 + KCH;
            #pragma unroll
            for (int j = 0; j < 2; j++) {
                int idx = tid + j*256;
                int m = idx >> 3, k8 = idx & 7;
                ah4[j] = ((const uint4*)(g_Sh + (size_t)m*CH + kn))[k8];
                al4[j] = ((const uint4*)(g_Sl + (size_t)m*CH + kn))[k8];
            }
            #pragma unroll
            for (int t = 0; t < 9; t++)
                w9[t] = conv_w[(size_t)t*CH*CH + (size_t)(kn + bi)*CH + o0 + ol];
            const float4* cp = (const float4*)&cst[(kn + bi)*NPIX];
            #pragma unroll
            for (int qd = 0; qd < 4; qd++) c4[qd] = cp[qd];
        }
        __syncthreads();                     // B: tiles ready

        // ---- MMA: 4 k-steps x 2mf x 2nf x 3 passes ----
        #pragma unroll
        for (int ks = 0; ks < 4; ks++) {
            const u32 kb = (u32)(ks*32);
            u32 ah[2][4], al[2][4];
            ldsm_x4(ah[0], ah_base + aOff + kb);
            ldsm_x4(ah[1], ah_base + aOff + 16*(APAD*2) + kb);
            ldsm_x4(al[0], al_base + aOff + kb);
            ldsm_x4(al[1], al_base + aOff + 16*(APAD*2) + kb);
            #pragma unroll
            for (int nf = 0; nf < 2; nf++) {
                u32 bh[2], bl[2];
                const u32 nb = (u32)(nf*8*(APAD*2));
                ldsm_x2(bh, bh_base + bOff + nb + kb);
                ldsm_x2(bl, bl_base + bOff + nb + kb);
                #pragma unroll
                for (int mf = 0; mf < 2; mf++) {
                    mma16816(acc[mf][nf], ah[mf], bh);
                    mma16816(acc[mf][nf], ah[mf], bl);
                    mma16816(acc[mf][nf], al[mf], bh);
                }
            }
        }
    }

    // ---- fused demod: one (b, og) per thread over full k=512 ----
    {
        const int db = tid & 63;
        const int dg = tid >> 6;
        float a2 = 1e-8f;
        const float4* sp = (const float4*)&g_s2[(size_t)db*CH];
        #pragma unroll 4
        for (int k4 = 0; k4 < CH/4; k4++) {
            float4 s2v = sp[k4];
            a2 = fmaf(s2v.x, q_s[k4*4+0][dg], a2);
            a2 = fmaf(s2v.y, q_s[k4*4+1][dg], a2);
            a2 = fmaf(s2v.z, q_s[k4*4+2][dg], a2);
            a2 = fmaf(s2v.w, q_s[k4*4+3][dg], a2);
        }
        float dv = rsqrtf(a2);
        __syncthreads();                     // all q_s reads done
        d_s[dg][db] = dv;
        // stage noise into q_s memory (reuse), bias, nstr
        ((float4*)q_s)[tid] = ((const float4*)noise)[tid];  // 1024 floats
        if (tid < 4) bias_s[tid] = bias[o0 + tid];
        if (tid == 4) nstr_s = ns_ptr[0];
    }
    __syncthreads();

    // ---- epilogue: demod, noise, bias, leaky-relu * sqrt(2) ----
    const float* nzp = (const float*)q_s;
    const float gain = 1.41421356237309515f;
    const float nstr = nstr_s;
    #pragma unroll
    for (int mf = 0; mf < 2; mf++) {
        #pragma unroll
        for (int nf = 0; nf < 2; nf++) {
            int row0 = wm*32 + mf*16 + (lane >> 2);
            int colb = wn*16 + nf*8 + 2*(lane & 3);
            int ol2 = colb >> 4;
            int px = colb & 15;
            float bb = bias_s[ol2];
            #pragma unroll
            for (int hh = 0; hh < 2; hh++) {
                int b = row0 + hh*8;
                float dv = d_s[ol2][b];
                float2 nz = *(const float2*)&nzp[b*NPIX + px];
                float x0 = acc[mf][nf][hh*2 + 0] * dv + nz.x*nstr + bb;
                float x1 = acc[mf][nf][hh*2 + 1] * dv + nz.y*nstr + bb;
                x0 = (x0 > 0.f ? x0 : 0.2f*x0) * gain;
                x1 = (x1 > 0.f ? x1 : 0.2f*x1) * gain;
                *(float2*)&out[(size_t)b*NCOL + n0 + colb] = make_float2(x0, x1);
            }
        }
    }
}

extern "C" void kernel_launch(void* const* d_in, const int* in_sizes, int n_in,
                              void* d_out, int out_size) {
    const float* w0     = (const float*)d_in[0];
    const float* cst    = (const float*)d_in[1];
    const float* conv_w = (const float*)d_in[2];
    const float* mod_w  = (const float*)d_in[3];
    const float* mod_b  = (const float*)d_in[4];
    const float* noise  = (const float*)d_in[5];
    const float* nstr   = (const float*)d_in[6];
    const float* bias   = (const float*)d_in[7];
    float* out = (float*)d_out;

    style_kernel<<<64, 256>>>(w0, mod_w, mod_b);
    mma_kernel<<<NCOL / TN, 256>>>(conv_w, cst, noise, nstr, bias, out);
}